// round 12
// baseline (speedup 1.0000x reference)
#include <cuda_runtime.h>
#include <cuda_bf16.h>
#include <cstdint>

#define HASH_SIZE 10240
#define PROJ_DIM  128
#define MODEL_DIM 512
#define NBATCH    8
#define SEQ       8192

// Fused table: fused[h][m] = scale * sum_k embed[h][k] * proj[m][k]  (21 MB)
__device__ float g_fused[HASH_SIZE * MODEL_DIM];

// Pre-converted split-bf16 operands in swizzled tile-image layout:
// 256B per row (16 x 16B chunks), chunk XOR-swizzled by (row&7).
__device__ __align__(16) unsigned char g_Ehi[HASH_SIZE * 256];
__device__ __align__(16) unsigned char g_Elo[HASH_SIZE * 256];
__device__ __align__(16) unsigned char g_Phi[MODEL_DIM * 256];
__device__ __align__(16) unsigned char g_Plo[MODEL_DIM * 256];

__device__ __forceinline__ uint32_t smem_u32(const void* p) {
    uint32_t a;
    asm("{ .reg .u64 t; cvta.to.shared.u64 t, %1; cvt.u32.u64 %0, t; }" : "=r"(a) : "l"(p));
    return a;
}
__device__ __forceinline__ void ldsm_x4(uint32_t& r0, uint32_t& r1,
                                        uint32_t& r2, uint32_t& r3, uint32_t addr) {
    asm volatile("ldmatrix.sync.aligned.m8n8.x4.shared.b16 {%0,%1,%2,%3}, [%4];"
                 : "=r"(r0), "=r"(r1), "=r"(r2), "=r"(r3) : "r"(addr));
}
__device__ __forceinline__ void mma_bf16(float* d, const uint32_t* a, const uint32_t* b) {
    asm volatile("mma.sync.aligned.m16n8k16.row.col.f32.bf16.bf16.f32 "
                 "{%0,%1,%2,%3}, {%4,%5,%6,%7}, {%8,%9}, {%0,%1,%2,%3};"
                 : "+f"(d[0]), "+f"(d[1]), "+f"(d[2]), "+f"(d[3])
                 : "r"(a[0]), "r"(a[1]), "r"(a[2]), "r"(a[3]), "r"(b[0]), "r"(b[1]));
}
__device__ __forceinline__ void cpa16(uint32_t dst, const void* src) {
    asm volatile("cp.async.cg.shared.global [%0], [%1], 16;" :: "r"(dst), "l"(src) : "memory");
}
__device__ __forceinline__ uint32_t sw(int row, int chunk) {
    return (uint32_t)(row * 256 + ((chunk ^ (row & 7)) << 4));
}

// ===========================================================================
// Kernel 0: one-shot split-bf16 conversion. 4 chunks/thread, loads batched
// first (MLP=8) -> latency-hiding. hi = truncated bf16 (PRMT), lo = rn(x-hi).
// ===========================================================================
__global__ __launch_bounds__(256) void convert_kernel(
    const float* __restrict__ E,
    const float* __restrict__ P)
{
    const int base = (blockIdx.x * 256 + threadIdx.x) * 4;
    const int ECH  = HASH_SIZE * 16;

    const float* srcs[4];
    unsigned char *hid[4], *lod[4];
    uint32_t offs[4];
    float4 va[4], vb[4];

    #pragma unroll
    for (int c = 0; c < 4; c++) {
        int idx = base + c;
        int row, chunk;
        if (idx < ECH) {
            row = idx >> 4; chunk = idx & 15;
            srcs[c] = E + (size_t)row * PROJ_DIM + chunk * 8;
            hid[c] = g_Ehi; lod[c] = g_Elo;
        } else {
            idx -= ECH;
            row = idx >> 4; chunk = idx & 15;
            srcs[c] = P + (size_t)row * PROJ_DIM + chunk * 8;
            hid[c] = g_Phi; lod[c] = g_Plo;
        }
        offs[c] = sw(row, chunk);
    }
    #pragma unroll
    for (int c = 0; c < 4; c++) {
        va[c] = __ldg((const float4*)srcs[c]);
        vb[c] = __ldg((const float4*)srcs[c] + 1);
    }
    #pragma unroll
    for (int c = 0; c < 4; c++) {
        float x[8] = {va[c].x, va[c].y, va[c].z, va[c].w,
                      vb[c].x, vb[c].y, vb[c].z, vb[c].w};
        uint32_t h[4], l[4];
        #pragma unroll
        for (int p = 0; p < 4; p++) {
            const uint32_t u0 = __float_as_uint(x[2 * p]);
            const uint32_t u1 = __float_as_uint(x[2 * p + 1]);
            asm("prmt.b32 %0, %1, %2, 0x7632;" : "=r"(h[p]) : "r"(u0), "r"(u1));
            const float r0 = x[2 * p]     - __uint_as_float(u0 & 0xffff0000u);
            const float r1 = x[2 * p + 1] - __uint_as_float(u1 & 0xffff0000u);
            __nv_bfloat162 t = __floats2bfloat162_rn(r0, r1);
            l[p] = *(uint32_t*)&t;
        }
        *(uint4*)(hid[c] + offs[c]) = make_uint4(h[0], h[1], h[2], h[3]);
        *(uint4*)(lod[c] + offs[c]) = make_uint4(l[0], l[1], l[2], l[3]);
    }
}

// ===========================================================================
// Kernel 1: persistent split-bf16 GEMM on mma.sync. 296 CTAs (2/SM).
// Tile M=128, N=64, K=128 full. 640 tiles m-major (t = m*8+n), contiguous
// chunks per CTA -> A slab reused across same-m tiles. cp.async copy-in.
// ===========================================================================
#define A_HI 0
#define A_LO 32768
#define B_HI 65536
#define B_LO 81920
#define SMEM_DYN (98304 + 1024)
#define NTILES 640
#define NCTA   296

__global__ __launch_bounds__(256) void build_table_kernel(
    const float* __restrict__ scale_p)
{
    extern __shared__ char smem_raw[];
    const uint32_t sb0   = smem_u32(smem_raw);
    const uint32_t pad   = ((sb0 + 1023) & ~1023u) - sb0;
    const uint32_t sbase = sb0 + pad;

    const int tid  = threadIdx.x;
    const int bid  = blockIdx.x;
    const int t0   = (bid * NTILES) / NCTA;
    const int t1   = ((bid + 1) * NTILES) / NCTA;
    const float s  = __ldg(scale_p);

    const int w    = tid >> 5;
    const int lane = tid & 31;
    const int wm   = w & 3;
    const int wn   = w >> 2;

    int rowA[2], rowB[2];
    #pragma unroll
    for (int mf = 0; mf < 2; mf++)
        rowA[mf] = wm * 32 + mf * 16 + (lane & 7) + (lane & 8);
    #pragma unroll
    for (int bp = 0; bp < 2; bp++)
        rowB[bp] = wn * 32 + bp * 16 + (lane & 7) + ((lane & 16) >> 1);
    const int ckA = lane >> 4;
    const int ckB = (lane >> 3) & 1;

    int cur_m = -1;
    for (int t = t0; t < t1; t++) {
        const int mi = t >> 3, ni = t & 7;
        const int m0 = mi * 128, n0 = ni * 64;

        // ---- async copy-in (A only on slab change)
        if (mi != cur_m) {
            const uint4* gAh = (const uint4*)(g_Ehi + (size_t)m0 * 256);
            const uint4* gAl = (const uint4*)(g_Elo + (size_t)m0 * 256);
            #pragma unroll
            for (int i = 0; i < 8; i++) {
                const int c = i * 256 + tid;
                cpa16(sbase + A_HI + c * 16, gAh + c);
                cpa16(sbase + A_LO + c * 16, gAl + c);
            }
            cur_m = mi;
        }
        {
            const uint4* gBh = (const uint4*)(g_Phi + (size_t)n0 * 256);
            const uint4* gBl = (const uint4*)(g_Plo + (size_t)n0 * 256);
            #pragma unroll
            for (int i = 0; i < 4; i++) {
                const int c = i * 256 + tid;
                cpa16(sbase + B_HI + c * 16, gBh + c);
                cpa16(sbase + B_LO + c * 16, gBl + c);
            }
        }
        asm volatile("cp.async.commit_group;" ::: "memory");
        asm volatile("cp.async.wait_group 0;" ::: "memory");
        __syncthreads();

        // ---- MMA mainloop
        float acc[2][4][4];
        #pragma unroll
        for (int mf = 0; mf < 2; mf++)
            #pragma unroll
            for (int nf = 0; nf < 4; nf++)
                #pragma unroll
                for (int q = 0; q < 4; q++) acc[mf][nf][q] = 0.0f;

        #pragma unroll
        for (int kk = 0; kk < 8; kk++) {
            uint32_t ah[2][4], al[2][4];
            #pragma unroll
            for (int mf = 0; mf < 2; mf++) {
                const uint32_t off = sw(rowA[mf], 2 * kk + ckA);
                ldsm_x4(ah[mf][0], ah[mf][1], ah[mf][2], ah[mf][3], sbase + A_HI + off);
                ldsm_x4(al[mf][0], al[mf][1], al[mf][2], al[mf][3], sbase + A_LO + off);
            }
            uint32_t bh[4][2], bl[4][2];
            #pragma unroll
            for (int bp = 0; bp < 2; bp++) {
                const uint32_t off = sw(rowB[bp], 2 * kk + ckB);
                ldsm_x4(bh[2 * bp][0], bh[2 * bp][1], bh[2 * bp + 1][0], bh[2 * bp + 1][1],
                        sbase + B_HI + off);
                ldsm_x4(bl[2 * bp][0], bl[2 * bp][1], bl[2 * bp + 1][0], bl[2 * bp + 1][1],
                        sbase + B_LO + off);
            }
            #pragma unroll
            for (int mf = 0; mf < 2; mf++)
                #pragma unroll
                for (int nf = 0; nf < 4; nf++) {
                    mma_bf16(acc[mf][nf], ah[mf], bh[nf]);
                    mma_bf16(acc[mf][nf], ah[mf], bl[nf]);
                    mma_bf16(acc[mf][nf], al[mf], bh[nf]);
                }
        }

        // ---- epilogue
        #pragma unroll
        for (int mf = 0; mf < 2; mf++) {
            const int r0 = m0 + wm * 32 + mf * 16 + (lane >> 2);
            #pragma unroll
            for (int nf = 0; nf < 4; nf++) {
                const int c = n0 + wn * 32 + nf * 8 + (lane & 3) * 2;
                float2 v0 = make_float2(acc[mf][nf][0] * s, acc[mf][nf][1] * s);
                float2 v1 = make_float2(acc[mf][nf][2] * s, acc[mf][nf][3] * s);
                __stcs((float2*)&g_fused[(size_t)r0 * MODEL_DIM + c], v0);
                __stcs((float2*)&g_fused[(size_t)(r0 + 8) * MODEL_DIM + c], v1);
            }
        }
        __syncthreads();   // protect smem before next tile's copy
    }
}

// ===========================================================================
// Kernel 2: hash + gather + stream out (LTS-bound near cap; unchanged).
// ===========================================================================
__device__ __forceinline__ int hash_at(const int* __restrict__ tok, int t) {
    const int s = t & (SEQ - 1);
    if (s == 0) return HASH_SIZE - 1;
    const int t1 = __ldg(tok + t);
    const int t0 = __ldg(tok + t - 1);
    // products < 2^31: no wrap; matches jnp.mod exactly
    return ((36313 * t1) ^ (27191 * t0)) % (HASH_SIZE - 1);
}

__global__ __launch_bounds__(256) void gather_kernel(
    const int* __restrict__ tok,
    float* __restrict__ out)
{
    const int warp = (blockIdx.x * 256 + threadIdx.x) >> 5;
    const int lane = threadIdx.x & 31;
    const int tA = warp * 2, tB = warp * 2 + 1;

    const int hA = hash_at(tok, tA);
    const int hB = hash_at(tok, tB);

    const float4* sA = (const float4*)(g_fused + (size_t)hA * MODEL_DIM);
    const float4* sB = (const float4*)(g_fused + (size_t)hB * MODEL_DIM);
    float4* dA = (float4*)(out + (size_t)tA * MODEL_DIM);
    float4* dB = (float4*)(out + (size_t)tB * MODEL_DIM);

    float4 a0 = __ldg(sA + lane);
    float4 a1 = __ldg(sA + lane + 32);
    float4 a2 = __ldg(sA + lane + 64);
    float4 a3 = __ldg(sA + lane + 96);
    float4 b0 = __ldg(sB + lane);
    float4 b1 = __ldg(sB + lane + 32);
    float4 b2 = __ldg(sB + lane + 64);
    float4 b3 = __ldg(sB + lane + 96);

    __stcs(dA + lane,      a0);
    __stcs(dA + lane + 32, a1);
    __stcs(dA + lane + 64, a2);
    __stcs(dA + lane + 96, a3);
    __stcs(dB + lane,      b0);
    __stcs(dB + lane + 32, b1);
    __stcs(dB + lane + 64, b2);
    __stcs(dB + lane + 96, b3);
}

// ===========================================================================
// Inputs (metadata order): token_ids(i32), embed_weight(f32), proj_weight(f32), scale(f32[1])
// ===========================================================================
extern "C" void kernel_launch(void* const* d_in, const int* in_sizes, int n_in,
                              void* d_out, int out_size)
{
    const int*   tok   = (const int*)d_in[0];
    const float* E     = (const float*)d_in[1];
    const float* P     = (const float*)d_in[2];
    const float* scale = (const float*)d_in[3];
    float*       out   = (float*)d_out;

    cudaFuncSetAttribute(build_table_kernel,
                         cudaFuncAttributeMaxDynamicSharedMemorySize, SMEM_DYN);

    const int nconv = (HASH_SIZE + MODEL_DIM) * 16 / 4;      // 43008 threads
    convert_kernel<<<nconv / 256, 256>>>(E, P);

    build_table_kernel<<<NCTA, 256, SMEM_DYN>>>(scale);

    gather_kernel<<<(NBATCH * SEQ) / 16, 256>>>(tok, out);
}

// round 14
// speedup vs baseline: 1.1905x; 1.1905x over previous
#include <cuda_runtime.h>
#include <cuda_fp16.h>
#include <cstdint>

#define HASH_SIZE 10240
#define PROJ_DIM  128
#define MODEL_DIM 512
#define NBATCH    8
#define SEQ       8192

// Fused table: fused[h][m] = scale * sum_k embed[h][k] * proj[m][k]  (21 MB)
__device__ float g_fused[HASH_SIZE * MODEL_DIM];

__device__ __forceinline__ uint32_t smem_u32(const void* p) {
    uint32_t a;
    asm("{ .reg .u64 t; cvta.to.shared.u64 t, %1; cvt.u32.u64 %0, t; }" : "=r"(a) : "l"(p));
    return a;
}
__device__ __forceinline__ void ldsm_x4(uint32_t& r0, uint32_t& r1,
                                        uint32_t& r2, uint32_t& r3, uint32_t addr) {
    asm volatile("ldmatrix.sync.aligned.m8n8.x4.shared.b16 {%0,%1,%2,%3}, [%4];"
                 : "=r"(r0), "=r"(r1), "=r"(r2), "=r"(r3) : "r"(addr));
}
__device__ __forceinline__ void mma_f16(float* d, const uint32_t* a, const uint32_t* b) {
    asm volatile("mma.sync.aligned.m16n8k16.row.col.f32.f16.f16.f32 "
                 "{%0,%1,%2,%3}, {%4,%5,%6,%7}, {%8,%9}, {%0,%1,%2,%3};"
                 : "+f"(d[0]), "+f"(d[1]), "+f"(d[2]), "+f"(d[3])
                 : "r"(a[0]), "r"(a[1]), "r"(a[2]), "r"(a[3]), "r"(b[0]), "r"(b[1]));
}
// byte offset of 16B chunk (row, chunk) in 256B-row swizzled layout
__device__ __forceinline__ uint32_t sw(int row, int chunk) {
    return (uint32_t)(row * 256 + ((chunk ^ (row & 7)) << 4));
}
// 8 fp32 -> 8 fp16 packed (one 16B chunk)
__device__ __forceinline__ uint4 cvt8_f16(float4 a, float4 b) {
    __half2 h0 = __floats2half2_rn(a.x, a.y);
    __half2 h1 = __floats2half2_rn(a.z, a.w);
    __half2 h2 = __floats2half2_rn(b.x, b.y);
    __half2 h3 = __floats2half2_rn(b.z, b.w);
    return make_uint4(*(uint32_t*)&h0, *(uint32_t*)&h1,
                      *(uint32_t*)&h2, *(uint32_t*)&h3);
}

// ===========================================================================
// Kernel 1: persistent fp16 GEMM on mma.sync (single product; fp16 u=2^-11
// with fp32 accumulation -> L2 rel err ~4e-4 < 1e-3).
// Conversion fused into copy phase (no separate convert kernel / scratch).
// Tile M=128, N=64, K=128 full. 296 CTAs (2/SM), m-major tiles, A-slab reuse.
// Smem: A 32 KB + B 16 KB fp16, 256B rows, chunk XOR-swizzle (row&7).
// ===========================================================================
#define A_OFF 0
#define B_OFF 32768
#define SMEM_DYN (49152 + 1024)
#define NTILES 640
#define NCTA   296

__global__ __launch_bounds__(256) void build_table_kernel(
    const float* __restrict__ E,
    const float* __restrict__ P,
    const float* __restrict__ scale_p)
{
    extern __shared__ char smem_raw[];
    const uint32_t sb0   = smem_u32(smem_raw);
    const uint32_t pad   = ((sb0 + 1023) & ~1023u) - sb0;
    char* smp            = smem_raw + pad;
    const uint32_t sbase = sb0 + pad;

    const int tid  = threadIdx.x;
    const int bid  = blockIdx.x;
    const int t0   = (bid * NTILES) / NCTA;
    const int t1   = ((bid + 1) * NTILES) / NCTA;
    const float s  = __ldg(scale_p);

    const int w    = tid >> 5;
    const int lane = tid & 31;
    const int wm   = w & 3;
    const int wn   = w >> 2;

    int rowA[2], rowB[2];
    #pragma unroll
    for (int mf = 0; mf < 2; mf++)
        rowA[mf] = wm * 32 + mf * 16 + (lane & 7) + (lane & 8);
    #pragma unroll
    for (int bp = 0; bp < 2; bp++)
        rowB[bp] = wn * 32 + bp * 16 + (lane & 7) + ((lane & 16) >> 1);
    const int ckA = lane >> 4;
    const int ckB = (lane >> 3) & 1;

    int cur_m = -1;
    for (int t = t0; t < t1; t++) {
        const int mi = t >> 3, ni = t & 7;
        const int m0 = mi * 128, n0 = ni * 64;

        // ---- copy+convert phase (A only on slab change)
        if (mi != cur_m) {
            #pragma unroll
            for (int i = 0; i < 8; i++) {
                const int idx = i * 256 + tid;           // 0..2047
                const int row = idx >> 4, chunk = idx & 15;
                const float4* g = (const float4*)(E + (size_t)(m0 + row) * PROJ_DIM + chunk * 8);
                uint4 v = cvt8_f16(__ldg(g), __ldg(g + 1));
                *(uint4*)(smp + A_OFF + sw(row, chunk)) = v;
            }
            cur_m = mi;
        }
        #pragma unroll
        for (int i = 0; i < 4; i++) {
            const int idx = i * 256 + tid;               // 0..1023
            const int row = idx >> 4, chunk = idx & 15;
            const float4* g = (const float4*)(P + (size_t)(n0 + row) * PROJ_DIM + chunk * 8);
            uint4 v = cvt8_f16(__ldg(g), __ldg(g + 1));
            *(uint4*)(smp + B_OFF + sw(row, chunk)) = v;
        }
        __syncthreads();

        // ---- MMA mainloop: 8 kk x (2 mf x 4 nf) = 64 HMMA / warp / tile
        float acc[2][4][4];
        #pragma unroll
        for (int mf = 0; mf < 2; mf++)
            #pragma unroll
            for (int nf = 0; nf < 4; nf++)
                #pragma unroll
                for (int q = 0; q < 4; q++) acc[mf][nf][q] = 0.0f;

        #pragma unroll
        for (int kk = 0; kk < 8; kk++) {
            uint32_t ah[2][4];
            #pragma unroll
            for (int mf = 0; mf < 2; mf++) {
                const uint32_t off = sw(rowA[mf], 2 * kk + ckA);
                ldsm_x4(ah[mf][0], ah[mf][1], ah[mf][2], ah[mf][3], sbase + A_OFF + off);
            }
            uint32_t bh[4][2];
            #pragma unroll
            for (int bp = 0; bp < 2; bp++) {
                const uint32_t off = sw(rowB[bp], 2 * kk + ckB);
                ldsm_x4(bh[2 * bp][0], bh[2 * bp][1], bh[2 * bp + 1][0], bh[2 * bp + 1][1],
                        sbase + B_OFF + off);
            }
            #pragma unroll
            for (int mf = 0; mf < 2; mf++)
                #pragma unroll
                for (int nf = 0; nf < 4; nf++)
                    mma_f16(acc[mf][nf], ah[mf], bh[nf]);
        }

        // ---- epilogue: scale + streaming store
        #pragma unroll
        for (int mf = 0; mf < 2; mf++) {
            const int r0 = m0 + wm * 32 + mf * 16 + (lane >> 2);
            #pragma unroll
            for (int nf = 0; nf < 4; nf++) {
                const int c = n0 + wn * 32 + nf * 8 + (lane & 3) * 2;
                float2 v0 = make_float2(acc[mf][nf][0] * s, acc[mf][nf][1] * s);
                float2 v1 = make_float2(acc[mf][nf][2] * s, acc[mf][nf][3] * s);
                __stcs((float2*)&g_fused[(size_t)r0 * MODEL_DIM + c], v0);
                __stcs((float2*)&g_fused[(size_t)(r0 + 8) * MODEL_DIM + c], v1);
            }
        }
        __syncthreads();   // protect smem before next tile's copy
    }
}

// ===========================================================================
// Kernel 2: hash + gather + stream out (LTS-bound near cap; unchanged).
// ===========================================================================
__device__ __forceinline__ int hash_at(const int* __restrict__ tok, int t) {
    const int s = t & (SEQ - 1);
    if (s == 0) return HASH_SIZE - 1;
    const int t1 = __ldg(tok + t);
    const int t0 = __ldg(tok + t - 1);
    // products < 2^31: no wrap; matches jnp.mod exactly
    return ((36313 * t1) ^ (27191 * t0)) % (HASH_SIZE - 1);
}

__global__ __launch_bounds__(256) void gather_kernel(
    const int* __restrict__ tok,
    float* __restrict__ out)
{
    const int warp = (blockIdx.x * 256 + threadIdx.x) >> 5;
    const int lane = threadIdx.x & 31;
    const int tA = warp * 2, tB = warp * 2 + 1;

    const int hA = hash_at(tok, tA);
    const int hB = hash_at(tok, tB);

    const float4* sA = (const float4*)(g_fused + (size_t)hA * MODEL_DIM);
    const float4* sB = (const float4*)(g_fused + (size_t)hB * MODEL_DIM);
    float4* dA = (float4*)(out + (size_t)tA * MODEL_DIM);
    float4* dB = (float4*)(out + (size_t)tB * MODEL_DIM);

    float4 a0 = __ldg(sA + lane);
    float4 a1 = __ldg(sA + lane + 32);
    float4 a2 = __ldg(sA + lane + 64);
    float4 a3 = __ldg(sA + lane + 96);
    float4 b0 = __ldg(sB + lane);
    float4 b1 = __ldg(sB + lane + 32);
    float4 b2 = __ldg(sB + lane + 64);
    float4 b3 = __ldg(sB + lane + 96);

    __stcs(dA + lane,      a0);
    __stcs(dA + lane + 32, a1);
    __stcs(dA + lane + 64, a2);
    __stcs(dA + lane + 96, a3);
    __stcs(dB + lane,      b0);
    __stcs(dB + lane + 32, b1);
    __stcs(dB + lane + 64, b2);
    __stcs(dB + lane + 96, b3);
}

// ===========================================================================
// Inputs (metadata order): token_ids(i32), embed_weight(f32), proj_weight(f32), scale(f32[1])
// ===========================================================================
extern "C" void kernel_launch(void* const* d_in, const int* in_sizes, int n_in,
                              void* d_out, int out_size)
{
    const int*   tok   = (const int*)d_in[0];
    const float* E     = (const float*)d_in[1];
    const float* P     = (const float*)d_in[2];
    const float* scale = (const float*)d_in[3];
    float*       out   = (float*)d_out;

    cudaFuncSetAttribute(build_table_kernel,
                         cudaFuncAttributeMaxDynamicSharedMemorySize, SMEM_DYN);

    build_table_kernel<<<NCTA, 256, SMEM_DYN>>>(E, P, scale);

    gather_kernel<<<(NBATCH * SEQ) / 16, 256>>>(tok, out);
}